// round 16
// baseline (speedup 1.0000x reference)
#include <cuda_runtime.h>
#include <cstdint>

#define B_SZ  4
#define S_LEN 2048
#define I_DIM 512
#define D_DIM 512
#define H_N   8
#define HD    64
#define P_DIM 720

// ---------------- scratch (device globals; no allocation allowed) -----------
__device__ float g_q[B_SZ * H_N * S_LEN * HD];      // [B,H,S,HD] (pre-scaled 1/HD)
__device__ float g_k[B_SZ * H_N * S_LEN * HD];
__device__ float g_v[B_SZ * H_N * S_LEN * HD];
__device__ float g_comb[B_SZ * S_LEN * D_DIM];      // [B,S,D]
__device__ float g_up[B_SZ * P_DIM * D_DIM];        // [B,P,D]

// ---------------- tf32 mma helpers ------------------------------------------
__device__ __forceinline__ unsigned f2t(float x) {
    unsigned r; asm("cvt.rna.tf32.f32 %0, %1;" : "=r"(r) : "f"(x)); return r;
}
__device__ __forceinline__ uint4 f2t4(float4 v) {
    return make_uint4(f2t(v.x), f2t(v.y), f2t(v.z), f2t(v.w));
}
__device__ __forceinline__ void mma8(float* c, const unsigned* a, const unsigned* b) {
    asm("mma.sync.aligned.m16n8k8.row.col.f32.tf32.tf32.f32 "
        "{%0,%1,%2,%3},{%4,%5,%6,%7},{%8,%9},{%0,%1,%2,%3};"
        : "+f"(c[0]), "+f"(c[1]), "+f"(c[2]), "+f"(c[3])
        : "r"(a[0]), "r"(a[1]), "r"(a[2]), "r"(a[3]), "r"(b[0]), "r"(b[1]));
}

#define GEMM_SMEM ((2 * 128 * 36 + 2 * 32 * 72) * 4)   // 55296 B, double-buffered

// =============================================================================
// QKV projection (one launch, z = {q,k,v}), double-buffered SMEM pipeline.
// Block tile 128(M) x 64(N), K-step 32, 8 warps. Q outputs pre-scaled by 1/HD.
// =============================================================================
__global__ __launch_bounds__(256) void qkv_tc(
    const float* __restrict__ X,
    const float* __restrict__ Wq, const float* __restrict__ bq,
    const float* __restrict__ Wk, const float* __restrict__ bk,
    const float* __restrict__ Wv, const float* __restrict__ bv)
{
    extern __shared__ __align__(16) unsigned dynq[];
    unsigned* As = dynq;                 // 2 x [128][36]
    unsigned* Bs = dynq + 2 * 128 * 36;  // 2 x [32][72]

    const int tid = threadIdx.x, lane = tid & 31, w = tid >> 5;
    const int g = lane >> 2, tg = lane & 3;
    const int m0 = blockIdx.x * 128;
    const int h  = blockIdx.y;
    const int sel = blockIdx.z;

    const float* W; const float* bias; float* Cp;
    if (sel == 0)      { W = Wq; bias = bq; Cp = g_q; }
    else if (sel == 1) { W = Wk; bias = bk; Cp = g_k; }
    else               { W = Wv; bias = bv; Cp = g_v; }
    const float* Bp = W + (size_t)h * I_DIM * HD;

    float4 rA[4], rB[2];
    auto loadA = [&](int k0) {
#pragma unroll
        for (int e = 0; e < 4; e++) {
            int idx = tid + e * 256, r = idx >> 3, c4 = idx & 7;
            rA[e] = *(const float4*)&X[(size_t)(m0 + r) * I_DIM + k0 + c4 * 4];
        }
    };
    auto loadB = [&](int k0) {
#pragma unroll
        for (int e = 0; e < 2; e++) {
            int idx = tid + e * 256, kk = idx >> 4, c4 = idx & 15;
            rB[e] = *(const float4*)&Bp[(size_t)(k0 + kk) * HD + c4 * 4];
        }
    };
    auto stsAB = [&](int buf) {
        unsigned* Ab = As + buf * (128 * 36);
        unsigned* Bb = Bs + buf * (32 * 72);
#pragma unroll
        for (int e = 0; e < 4; e++) {
            int idx = tid + e * 256, r = idx >> 3, c4 = idx & 7;
            *(uint4*)&Ab[r * 36 + c4 * 4] = f2t4(rA[e]);
        }
#pragma unroll
        for (int e = 0; e < 2; e++) {
            int idx = tid + e * 256, kk = idx >> 4, c4 = idx & 15;
            *(uint4*)&Bb[kk * 72 + c4 * 4] = f2t4(rB[e]);
        }
    };

    constexpr int NIT = I_DIM / 32;
    loadA(0); loadB(0);
    stsAB(0);
    loadA(32); loadB(32);
    __syncthreads();

    float acc[8][4] = {};
    const int mw = w * 16;

    for (int it = 0; it < NIT; it++) {
        int buf = it & 1;
        if (it + 1 < NIT) stsAB(buf ^ 1);               // regs hold tile it+1
        if (it + 2 < NIT) { loadA((it + 2) * 32); loadB((it + 2) * 32); }
        const unsigned* Ab = As + buf * (128 * 36);
        const unsigned* Bb = Bs + buf * (32 * 72);
#pragma unroll
        for (int kt = 0; kt < 4; kt++) {
            const unsigned* ap = &Ab[(mw + g) * 36 + kt * 8 + tg];
            unsigned a[4] = {ap[0], ap[8 * 36], ap[4], ap[8 * 36 + 4]};
#pragma unroll
            for (int nt = 0; nt < 8; nt++) {
                const unsigned* bp = &Bb[(kt * 8 + tg) * 72 + nt * 8 + g];
                unsigned b[2] = {bp[0], bp[4 * 72]};
                mma8(acc[nt], a, b);
            }
        }
        __syncthreads();
    }

    const float osc = (sel == 0) ? (1.0f / (float)HD) : 1.0f;   // fold 1/HD into Q
#pragma unroll
    for (int hh = 0; hh < 2; hh++) {
        int r = m0 + mw + g + 8 * hh;
        int bb = r >> 11, s = r & (S_LEN - 1);
        float* dst = Cp + ((size_t)(bb * H_N + h) * S_LEN + s) * HD;
#pragma unroll
        for (int nt = 0; nt < 8; nt++) {
            int c = nt * 8 + 2 * tg;
            *(float2*)&dst[c] = make_float2(
                (acc[nt][2 * hh]     + bias[h * HD + c])     * osc,
                (acc[nt][2 * hh + 1] + bias[h * HD + c + 1]) * osc);
        }
    }
}

// =============================================================================
// Templated tensor-core GEMM (temporal / output), double-buffered pipeline.
// MODE 1: temp A=Wt[720,2048]     B=g_comb[b][2048,512]    C=g_up, row bias
// MODE 2: out  A=g_up[2880,512]   B[k][n]=Wo[n][k] (trans) C=d_out, col bias
// =============================================================================
template<int MODE>
__global__ __launch_bounds__(256) void gemm_tc(
    const float* __restrict__ A, const float* __restrict__ Bx,
    const float* __restrict__ bias, float* __restrict__ Cext)
{
    constexpr int K   = (MODE == 1) ? 2048 : 512;
    constexpr int LDA = (MODE == 1) ? 2048 : 512;
    constexpr int MR  = (MODE == 1) ? 720 : 2880;

    extern __shared__ __align__(16) unsigned dyng[];
    unsigned* As = dyng;                 // 2 x [128][36]
    unsigned* Bs = dyng + 2 * 128 * 36;  // 2 x [32][72]

    const int tid = threadIdx.x, lane = tid & 31, w = tid >> 5;
    const int g = lane >> 2, tg = lane & 3;
    const int m0 = blockIdx.x * 128;
    const int n0 = blockIdx.y * 64;

    const float* Ap = (MODE == 2) ? g_up : A;
    const float* Bp;
    float* Cp;
    if (MODE == 1) {
        Bp = g_comb + (size_t)blockIdx.z * S_LEN * D_DIM;
        Cp = g_up + (size_t)blockIdx.z * P_DIM * D_DIM;
    } else {
        Bp = Bx;
        Cp = Cext;
    }

    float4 rA[4], rB[2];
    auto loadA = [&](int k0) {
#pragma unroll
        for (int e = 0; e < 4; e++) {
            int idx = tid + e * 256, r = idx >> 3, c4 = idx & 7;
            int gm = m0 + r;
            rA[e] = (gm < MR) ? *(const float4*)&Ap[(size_t)gm * LDA + k0 + c4 * 4]
                              : make_float4(0.f, 0.f, 0.f, 0.f);
        }
    };
    auto loadB = [&](int k0) {
        if (MODE != 2) {
#pragma unroll
            for (int e = 0; e < 2; e++) {
                int idx = tid + e * 256, kk = idx >> 4, c4 = idx & 15;
                rB[e] = *(const float4*)&Bp[(size_t)(k0 + kk) * 512 + n0 + c4 * 4];
            }
        } else {
#pragma unroll
            for (int e = 0; e < 2; e++) {
                int idx = tid + e * 256, c = idx >> 3, j = idx & 7;
                rB[e] = *(const float4*)&Bp[(size_t)(n0 + c) * 512 + k0 + j * 4];
            }
        }
    };
    auto stsAB = [&](int buf) {
        unsigned* Ab = As + buf * (128 * 36);
        unsigned* Bb = Bs + buf * (32 * 72);
#pragma unroll
        for (int e = 0; e < 4; e++) {
            int idx = tid + e * 256, r = idx >> 3, c4 = idx & 7;
            *(uint4*)&Ab[r * 36 + c4 * 4] = f2t4(rA[e]);
        }
        if (MODE != 2) {
#pragma unroll
            for (int e = 0; e < 2; e++) {
                int idx = tid + e * 256, kk = idx >> 4, c4 = idx & 15;
                *(uint4*)&Bb[kk * 72 + c4 * 4] = f2t4(rB[e]);
            }
        } else {
#pragma unroll
            for (int e = 0; e < 2; e++) {
                int idx = tid + e * 256, c = idx >> 3, j = idx & 7;
                Bb[(4 * j + 0) * 72 + c] = f2t(rB[e].x);
                Bb[(4 * j + 1) * 72 + c] = f2t(rB[e].y);
                Bb[(4 * j + 2) * 72 + c] = f2t(rB[e].z);
                Bb[(4 * j + 3) * 72 + c] = f2t(rB[e].w);
            }
        }
    };

    constexpr int NIT = K / 32;
    loadA(0); loadB(0);
    stsAB(0);
    loadA(32); loadB(32);
    __syncthreads();

    float acc[8][4] = {};
    const int mw = w * 16;

    for (int it = 0; it < NIT; it++) {
        int buf = it & 1;
        if (it + 1 < NIT) stsAB(buf ^ 1);
        if (it + 2 < NIT) { loadA((it + 2) * 32); loadB((it + 2) * 32); }
        const unsigned* Ab = As + buf * (128 * 36);
        const unsigned* Bb = Bs + buf * (32 * 72);
#pragma unroll
        for (int kt = 0; kt < 4; kt++) {
            const unsigned* ap = &Ab[(mw + g) * 36 + kt * 8 + tg];
            unsigned a[4] = {ap[0], ap[8 * 36], ap[4], ap[8 * 36 + 4]};
#pragma unroll
            for (int nt = 0; nt < 8; nt++) {
                const unsigned* bp = &Bb[(kt * 8 + tg) * 72 + nt * 8 + g];
                unsigned b[2] = {bp[0], bp[4 * 72]};
                mma8(acc[nt], a, b);
            }
        }
        __syncthreads();
    }

#pragma unroll
    for (int hh = 0; hh < 2; hh++) {
        int r = m0 + mw + g + 8 * hh;
        if (r < MR) {
            float* dst = Cp + (size_t)r * 512 + n0;
            float rb = (MODE == 1) ? bias[r] : 0.f;
#pragma unroll
            for (int nt = 0; nt < 8; nt++) {
                int c = nt * 8 + 2 * tg;
                float b0, b1;
                if (MODE == 1) { b0 = rb;           b1 = rb; }
                else           { b0 = bias[n0 + c]; b1 = bias[n0 + c + 1]; }
                *(float2*)&dst[c] =
                    make_float2(acc[nt][2 * hh] + b0, acc[nt][2 * hh + 1] + b1);
            }
        }
    }
}

// =============================================================================
// Flash attention on tensor cores, v4: STS/mma overlap without extra SMEM.
// Ks and Vs have disjoint consumption phases, so:
//   iter t: [STS V(t) + LDG V(t+1)] overlap S-mma(t)  -> softmax -> sync#1
//           [STS K(t+1) + LDG K(t+2)] overlap PV-mma(t) -> sync#2
// SMEM: Qs[128][68] + Ks[64][68] + Vs[64][72] + Pw 8x[16][68] = 105472 B.
// =============================================================================
#define ATTN_SMEM ((128 * 68 + 64 * 68 + 64 * 72 + 8 * 16 * 68) * 4)

__global__ __launch_bounds__(256, 2) void attn_tc()
{
    extern __shared__ __align__(16) unsigned sm[];
    unsigned* Qs = sm;                       // [128][68]
    unsigned* Ks = sm + 128 * 68;            // [64][68]
    unsigned* Vs = Ks + 64 * 68;             // [64][72]
    unsigned* Pw = Vs + 64 * 72;             // 8 x [16][68]

    const int tid = threadIdx.x, lane = tid & 31, w = tid >> 5;
    const int g = lane >> 2, tg = lane & 3;
    const int q0 = blockIdx.x * 128, bh = blockIdx.y;

    const float* Qg = g_q + (size_t)bh * S_LEN * HD;
    const float* Kg = g_k + (size_t)bh * S_LEN * HD;
    const float* Vg = g_v + (size_t)bh * S_LEN * HD;

    float4 rK[4], rV[4];
    auto loadK = [&](int t) {
        const float* Kt = Kg + (size_t)t * 64 * HD;
#pragma unroll
        for (int e = 0; e < 4; e++) {
            int idx = tid + e * 256, r = idx >> 4, c4 = idx & 15;
            rK[e] = *(const float4*)&Kt[(size_t)r * HD + c4 * 4];
        }
    };
    auto loadV = [&](int t) {
        const float* Vt = Vg + (size_t)t * 64 * HD;
#pragma unroll
        for (int e = 0; e < 4; e++) {
            int idx = tid + e * 256, r = idx >> 4, c4 = idx & 15;
            rV[e] = *(const float4*)&Vt[(size_t)r * HD + c4 * 4];
        }
    };
    auto stsK = [&]() {
#pragma unroll
        for (int e = 0; e < 4; e++) {
            int idx = tid + e * 256, r = idx >> 4, c4 = idx & 15;
            *(uint4*)&Ks[r * 68 + c4 * 4] = f2t4(rK[e]);
        }
    };
    auto stsV = [&]() {
#pragma unroll
        for (int e = 0; e < 4; e++) {
            int idx = tid + e * 256, r = idx >> 4, c4 = idx & 15;
            *(uint4*)&Vs[r * 72 + c4 * 4] = f2t4(rV[e]);
        }
    };

    // prologue: stage Q (already 1/HD-scaled at projection), K0; prefetch K1, V0
    loadK(0);
    loadV(0);
#pragma unroll
    for (int e = 0; e < 8; e++) {
        int idx = tid + e * 256, r = idx >> 4, c4 = idx & 15;
        float4 q = *(const float4*)&Qg[(size_t)(q0 + r) * HD + c4 * 4];
        *(uint4*)&Qs[r * 68 + c4 * 4] = f2t4(q);
    }
    stsK();
    loadK(1);
    __syncthreads();

    float oa[8][4] = {};
    float l0 = 0.f, l1 = 0.f;
    unsigned* pw = Pw + w * 16 * 68;
    const unsigned* qbase = &Qs[(w * 16 + g) * 68];
    constexpr int NT = S_LEN / 64;

    for (int t = 0; t < NT; t++) {
        // ---- STS V(t) + LDG V(t+1), overlapping S-mma --------------------------
        stsV();
        if (t + 1 < NT) loadV(t + 1);

        // ---- S = Q @ K^T (reads Ks = K(t)) --------------------------------------
        float sfr[8][4] = {};
#pragma unroll
        for (int kt = 0; kt < 8; kt++) {
            const unsigned* ap = qbase + kt * 8 + tg;
            unsigned a[4] = {ap[0], ap[8 * 68], ap[4], ap[8 * 68 + 4]};
#pragma unroll
            for (int nt = 0; nt < 8; nt++) {
                const unsigned* kp = &Ks[(nt * 8 + g) * 68 + kt * 8 + tg];
                unsigned b[2] = {kp[0], kp[4]};
                mma8(sfr[nt], a, b);
            }
        }

        // ---- softmax-lite: p = exp(s); per-thread l; P to per-warp SMEM ---------
#pragma unroll
        for (int nt = 0; nt < 8; nt++) {
            float p0 = __expf(sfr[nt][0]), p1 = __expf(sfr[nt][1]);
            float p2 = __expf(sfr[nt][2]), p3 = __expf(sfr[nt][3]);
            l0 += p0 + p1;
            l1 += p2 + p3;
            *(uint2*)&pw[g * 68 + nt * 8 + 2 * tg]       = make_uint2(f2t(p0), f2t(p1));
            *(uint2*)&pw[(g + 8) * 68 + nt * 8 + 2 * tg] = make_uint2(f2t(p2), f2t(p3));
        }

        __syncthreads();   // #1: Vs written by all; Ks reads done by all

        // ---- STS K(t+1) + LDG K(t+2), overlapping PV-mma ------------------------
        if (t + 1 < NT) stsK();
        if (t + 2 < NT) loadK(t + 2);

        // ---- O += P @ V (reads Vs = V(t), pw) ------------------------------------
#pragma unroll
        for (int kt = 0; kt < 8; kt++) {
            const unsigned* pp = pw + kt * 8 + tg;
            unsigned pa[4] = {pp[g * 68], pp[(g + 8) * 68],
                              pp[g * 68 + 4], pp[(g + 8) * 68 + 4]};
#pragma unroll
            for (int nt = 0; nt < 8; nt++) {
                const unsigned* vp = &Vs[(kt * 8 + tg) * 72 + nt * 8 + g];
                unsigned b[2] = {vp[0], vp[4 * 72]};
                mma8(oa[nt], pa, b);
            }
        }

        __syncthreads();   // #2: Ks written by all; Vs reads done by all
    }

    // ---- final l reduction + epilogue ----------------------------------------
    l0 += __shfl_xor_sync(0xffffffffu, l0, 1);
    l0 += __shfl_xor_sync(0xffffffffu, l0, 2);
    l1 += __shfl_xor_sync(0xffffffffu, l1, 1);
    l1 += __shfl_xor_sync(0xffffffffu, l1, 2);
    const float inv0 = 1.0f / l0, inv1 = 1.0f / l1;

    const int bb = bh >> 3, hh = bh & 7;
    const int r0 = q0 + w * 16 + g;
    float* d0 = g_comb + ((size_t)bb * S_LEN + r0) * D_DIM + hh * HD;
    float* d1 = g_comb + ((size_t)bb * S_LEN + r0 + 8) * D_DIM + hh * HD;
#pragma unroll
    for (int nt = 0; nt < 8; nt++) {
        int c = nt * 8 + 2 * tg;
        *(float2*)&d0[c] = make_float2(oa[nt][0] * inv0, oa[nt][1] * inv0);
        *(float2*)&d1[c] = make_float2(oa[nt][2] * inv1, oa[nt][3] * inv1);
    }
}

// =============================================================================
// launch
// =============================================================================
extern "C" void kernel_launch(void* const* d_in, const int* in_sizes, int n_in,
                              void* d_out, int out_size)
{
    const float* X  = (const float*)d_in[0];
    const float* Wq = (const float*)d_in[1];
    const float* bq = (const float*)d_in[2];
    const float* Wk = (const float*)d_in[3];
    const float* bk = (const float*)d_in[4];
    const float* Wv = (const float*)d_in[5];
    const float* bv = (const float*)d_in[6];
    const float* Wt = (const float*)d_in[7];
    const float* bt = (const float*)d_in[8];
    const float* Wo = (const float*)d_in[9];
    const float* bo = (const float*)d_in[10];
    float* out = (float*)d_out;

    (void)in_sizes; (void)n_in; (void)out_size;

    cudaFuncSetAttribute(qkv_tc,
                         cudaFuncAttributeMaxDynamicSharedMemorySize, GEMM_SMEM);
    cudaFuncSetAttribute(gemm_tc<1>,
                         cudaFuncAttributeMaxDynamicSharedMemorySize, GEMM_SMEM);
    cudaFuncSetAttribute(gemm_tc<2>,
                         cudaFuncAttributeMaxDynamicSharedMemorySize, GEMM_SMEM);
    cudaFuncSetAttribute(attn_tc,
                         cudaFuncAttributeMaxDynamicSharedMemorySize, ATTN_SMEM);

    qkv_tc<<<dim3(64, 8, 3), 256, GEMM_SMEM>>>(X, Wq, bq, Wk, bk, Wv, bv);
    attn_tc<<<dim3(S_LEN / 128, B_SZ * H_N), 256, ATTN_SMEM>>>();
    gemm_tc<1><<<dim3(6, D_DIM / 64, B_SZ), 256, GEMM_SMEM>>>(Wt, nullptr, bt, nullptr);
    gemm_tc<2><<<dim3(23, I_DIM / 64), 256, GEMM_SMEM>>>(nullptr, Wo, bo, out);
}